// round 17
// baseline (speedup 1.0000x reference)
#include <cuda_runtime.h>
#include <math.h>
#include <stdint.h>

#define BB 32
#define FF 4096
#define HH 32
#define DD 128
#define LL 8192
#define NSPLIT 32
#define CH (LL/NSPLIT)          /* 256 */
#define WIN 32
#define LDW 40                  /* K window stride (floats) */
#define LDV 36                  /* V window stride (floats) */
#define LDP 36                  /* psh row stride (col 32 = corr) */
#define SCALE 0.08838834764831845f

/* ---------------- scratch ------------------------------------------------ */
__device__ float g_q[BB*HH*DD];     /* zeroed at end of each call (ogemm) */
__device__ float g_qf[BB*HH*DD];
__device__ float g_k[BB*DD];
__device__ float g_kr[BB*DD];
__device__ float g_v[BB*DD];
__device__ float g_attn[BB*HH*DD];
__device__ float g_pm[BB*NSPLIT*HH];
__device__ float g_psum[BB*NSPLIT*HH];
__device__ float g_po[BB*NSPLIT*HH*DD];
__device__ float g_freq[64];

/* ---------------- helpers ------------------------------------------------ */
__device__ __forceinline__ uint32_t s2u(const void* p) {
    return (uint32_t)__cvta_generic_to_shared(p);
}
__device__ __forceinline__ void cpa16(uint32_t s, const void* g) {
    asm volatile("cp.async.cg.shared.global [%0], [%1], 16;" :: "r"(s), "l"(g));
}
__device__ __forceinline__ void cpcommit() { asm volatile("cp.async.commit_group;"); }
__device__ __forceinline__ void cpwait0()  { asm volatile("cp.async.wait_group 0;"); }
__device__ __forceinline__ void cpwait1()  { asm volatile("cp.async.wait_group 1;"); }

__device__ __forceinline__ uint32_t f2tf(float x) {
    uint32_t r; asm("cvt.rna.tf32.f32 %0, %1;" : "=r"(r) : "f"(x)); return r;
}
__device__ __forceinline__ float tff(float x) { return __uint_as_float(f2tf(x)); }
__device__ __forceinline__ void mma8(float* d, const uint32_t* a, const uint32_t* b) {
    asm volatile("mma.sync.aligned.m16n8k8.row.col.f32.tf32.tf32.f32 "
        "{%0,%1,%2,%3},{%4,%5,%6,%7},{%8,%9},{%0,%1,%2,%3};"
        : "+f"(d[0]), "+f"(d[1]), "+f"(d[2]), "+f"(d[3])
        : "r"(a[0]), "r"(a[1]), "r"(a[2]), "r"(a[3]), "r"(b[0]), "r"(b[1]));
}

/* ---------------- fused q-proj tgemm (0..255) + kvproj (256..319) --------- */
#define SPLITK 16
#define KSL (FF/SPLITK)          /* 256 */
__global__ __launch_bounds__(256, 2) void qkvproj_kernel(
        const float* __restrict__ A, const float* __restrict__ Wq,
        const float* __restrict__ Wk, const float* __restrict__ Wv,
        float* __restrict__ Cq) {
    extern __shared__ float sm[];
    int bx = blockIdx.x;
    int t = threadIdx.x;

    if (bx >= 256) {
        /* freq table (exact double-rounded values), hidden under the wave */
        if (bx == 256 && t < 64)
            g_freq[t] = (float)exp(-(double)t * 0.14391156831212787);

        int kv = bx - 256;
        const float* W = (kv >> 5) ? Wv : Wk;
        float* C = (kv >> 5) ? g_v : g_k;
        int k0 = (kv & 31) * 128;
        float* As = sm;
        float* Ws = sm + 32 * 36;
        int mi = t >> 5, ni = t & 31;
        float acc[4][4];
#pragma unroll
        for (int i = 0; i < 4; i++)
#pragma unroll
            for (int j = 0; j < 4; j++) acc[i][j] = 0.f;

        for (int kb = 0; kb < 128; kb += 32) {
            int kg = k0 + kb;
#pragma unroll
            for (int p = 0; p < 4; p++) {
                int i = t + p * 256;
                As[(i & 31) * 36 + (i >> 5)] = A[(i >> 5) * FF + kg + (i & 31)];
            }
#pragma unroll
            for (int p = 0; p < 4; p++) {
                int i = t + p * 256;
                int kk = i >> 5, nq = i & 31;
                *(float4*)&Ws[kk * 132 + nq * 4] =
                    *(const float4*)&W[(kg + kk) * DD + nq * 4];
            }
            __syncthreads();
#pragma unroll
            for (int kk = 0; kk < 32; kk++) {
                float4 a = *(float4*)&As[kk * 36 + mi * 4];
                float4 w = *(float4*)&Ws[kk * 132 + ni * 4];
                acc[0][0] += a.x*w.x; acc[0][1] += a.x*w.y; acc[0][2] += a.x*w.z; acc[0][3] += a.x*w.w;
                acc[1][0] += a.y*w.x; acc[1][1] += a.y*w.y; acc[1][2] += a.y*w.z; acc[1][3] += a.y*w.w;
                acc[2][0] += a.z*w.x; acc[2][1] += a.z*w.y; acc[2][2] += a.z*w.z; acc[2][3] += a.z*w.w;
                acc[3][0] += a.w*w.x; acc[3][1] += a.w*w.y; acc[3][2] += a.w*w.z; acc[3][3] += a.w*w.w;
            }
            __syncthreads();
        }
#pragma unroll
        for (int i = 0; i < 4; i++)
#pragma unroll
            for (int j = 0; j < 4; j++)
                atomicAdd(&C[(mi * 4 + i) * DD + ni * 4 + j], acc[i][j]);
        return;
    }

    /* q-proj branch: 2-term A x single-term W */
    float* As = sm;
    float* Ws = sm + 8448;
    uint32_t ws_u = s2u(Ws);

    int n0 = (bx & 15) * 256;
    int k0 = (bx >> 4) * KSL;
    int wp = t >> 5, lane = t & 31;
    int g = lane >> 2, c = lane & 3;

#pragma unroll
    for (int p = 0; p < 32; p++) {
        int i = t + p * 256;
        int m = i >> 8, k = i & 255;
        As[k * 33 + m] = A[m * FF + k0 + k];
    }
    auto loadW = [&](int kb, int buf) {
        const float* src = Wq + (size_t)(k0 + kb * 32) * FF + n0;
#pragma unroll
        for (int p = 0; p < 8; p++) {
            int ci = t + p * 256;
            int kk = ci >> 6, u = ci & 63;
            cpa16(ws_u + (uint32_t)(buf * 8448 + kk * 264 + 4 * u) * 4,
                  src + (size_t)kk * FF + 4 * u);
        }
        cpcommit();
    };
    loadW(0, 0);
    loadW(1, 1);

    float acc[2][4][4];
#pragma unroll
    for (int mt = 0; mt < 2; mt++)
#pragma unroll
        for (int nt = 0; nt < 4; nt++)
#pragma unroll
            for (int r = 0; r < 4; r++) acc[mt][nt][r] = 0.f;

    for (int kb = 0; kb < 8; kb++) {
        if (kb == 7) cpwait0(); else cpwait1();
        __syncthreads();
        const float* wsb = Ws + (kb & 1) * 8448;

#pragma unroll
        for (int ks = 0; ks < 4; ks++) {
            int kg = kb * 32 + ks * 8;
            uint32_t ahi[2][4], alo[2][4];
#pragma unroll
            for (int mt = 0; mt < 2; mt++) {
                float a0 = As[(kg + c)     * 33 + mt * 16 + g];
                float a1 = As[(kg + c)     * 33 + mt * 16 + g + 8];
                float a2 = As[(kg + c + 4) * 33 + mt * 16 + g];
                float a3 = As[(kg + c + 4) * 33 + mt * 16 + g + 8];
                ahi[mt][0] = f2tf(a0);
                ahi[mt][1] = f2tf(a1);
                ahi[mt][2] = f2tf(a2);
                ahi[mt][3] = f2tf(a3);
                alo[mt][0] = f2tf(a0 - __uint_as_float(ahi[mt][0]));
                alo[mt][1] = f2tf(a1 - __uint_as_float(ahi[mt][1]));
                alo[mt][2] = f2tf(a2 - __uint_as_float(ahi[mt][2]));
                alo[mt][3] = f2tf(a3 - __uint_as_float(ahi[mt][3]));
            }
#pragma unroll
            for (int nt = 0; nt < 4; nt++) {
                float b0 = wsb[(ks * 8 + c)     * 264 + wp * 32 + nt * 8 + g];
                float b1 = wsb[(ks * 8 + c + 4) * 264 + wp * 32 + nt * 8 + g];
                uint32_t bhi[2] = {f2tf(b0), f2tf(b1)};
#pragma unroll
                for (int mt = 0; mt < 2; mt++) {
                    mma8(acc[mt][nt], ahi[mt], bhi);
                    mma8(acc[mt][nt], alo[mt], bhi);
                }
            }
        }
        __syncthreads();
        if (kb < 6) loadW(kb + 2, kb & 1);
    }
#pragma unroll
    for (int mt = 0; mt < 2; mt++)
#pragma unroll
        for (int nt = 0; nt < 4; nt++) {
            int row = mt * 16 + g;
            int col = n0 + wp * 32 + nt * 8 + 2 * c;
            atomicAdd(&Cq[(row)     * FF + col],     acc[mt][nt][0]);
            atomicAdd(&Cq[(row)     * FF + col + 1], acc[mt][nt][1]);
            atomicAdd(&Cq[(row + 8) * FF + col],     acc[mt][nt][2]);
            atomicAdd(&Cq[(row + 8) * FF + col + 1], acc[mt][nt][3]);
        }
}

/* ---------------- o-proj tgemm + scratch zeroing (blockIdx.y == 16) ------- */
__global__ __launch_bounds__(256, 2) void ogemm_kernel(
        const float* __restrict__ A, const float* __restrict__ W,
        float* __restrict__ C) {
    extern __shared__ float sm[];
    int t = threadIdx.x;

    if (blockIdx.y == 16) {      /* zero scratch for the NEXT graph replay */
        int base = blockIdx.x * 256 + t;     /* 0..4095 */
#pragma unroll
        for (int p = 0; p < 32; p++) g_q[base + p * 4096] = 0.f;
        g_k[base] = 0.f;
        g_v[base] = 0.f;
        return;
    }

    float* As = sm;
    float* Ws = sm + 8448;
    const float4* As4 = (const float4*)As;
    uint32_t ws_u = s2u(Ws);

    int n0 = blockIdx.x * 256;
    int k0 = blockIdx.y * KSL;
    int wp = t >> 5, lane = t & 31;
    int g = lane >> 2, c = lane & 3;

#pragma unroll
    for (int p = 0; p < 32; p++) {
        int i = t + p * 256;
        int m = i >> 8, k = i & 255;
        float val = tff(A[m * FF + k0 + k]);
        int kslot = k >> 3, c2 = k & 3, hi4 = (k >> 2) & 1;
        int mt = m >> 4, g2 = m & 7, m8 = (m >> 3) & 1;
        int fidx = (kslot * 2 + mt) * 32 + c2 * 8 + ((g2 + 2 * c2) & 7);
        As[fidx * 4 + hi4 * 2 + m8] = val;
    }
    auto loadW = [&](int kb, int buf) {
        const float* src = W + (size_t)(k0 + kb * 32) * FF + n0;
#pragma unroll
        for (int p = 0; p < 8; p++) {
            int ci = t + p * 256;
            int kk = ci >> 6, u = ci & 63;
            cpa16(ws_u + (uint32_t)(buf * 8448 + kk * 264 + 4 * u) * 4,
                  src + (size_t)kk * FF + 4 * u);
        }
        cpcommit();
    };
    loadW(0, 0);
    loadW(1, 1);

    int swz = c * 8 + ((g + 2 * c) & 7);

    float acc[2][4][4];
#pragma unroll
    for (int mt = 0; mt < 2; mt++)
#pragma unroll
        for (int nt = 0; nt < 4; nt++)
#pragma unroll
            for (int r = 0; r < 4; r++) acc[mt][nt][r] = 0.f;

    for (int kb = 0; kb < 8; kb++) {
        if (kb == 7) cpwait0(); else cpwait1();
        __syncthreads();
        const float* wsb = Ws + (kb & 1) * 8448;

#pragma unroll
        for (int ks = 0; ks < 4; ks++) {
            int kslot = kb * 4 + ks;
            uint32_t ahi[2][4];
            float4 af0 = As4[(kslot * 2 + 0) * 32 + swz];
            float4 af1 = As4[(kslot * 2 + 1) * 32 + swz];
            ahi[0][0] = __float_as_uint(af0.x); ahi[0][1] = __float_as_uint(af0.y);
            ahi[0][2] = __float_as_uint(af0.z); ahi[0][3] = __float_as_uint(af0.w);
            ahi[1][0] = __float_as_uint(af1.x); ahi[1][1] = __float_as_uint(af1.y);
            ahi[1][2] = __float_as_uint(af1.z); ahi[1][3] = __float_as_uint(af1.w);
#pragma unroll
            for (int nt = 0; nt < 4; nt++) {
                float b0 = wsb[(ks * 8 + c)     * 264 + wp * 32 + nt * 8 + g];
                float b1 = wsb[(ks * 8 + c + 4) * 264 + wp * 32 + nt * 8 + g];
                uint32_t bhi[2] = {f2tf(b0), f2tf(b1)};
                mma8(acc[0][nt], ahi[0], bhi);
                mma8(acc[1][nt], ahi[1], bhi);
            }
        }
        __syncthreads();
        if (kb < 6) loadW(kb + 2, kb & 1);
    }
#pragma unroll
    for (int mt = 0; mt < 2; mt++)
#pragma unroll
        for (int nt = 0; nt < 4; nt++) {
            int row = mt * 16 + g;
            int col = n0 + wp * 32 + nt * 8 + 2 * c;
            atomicAdd(&C[(row)     * FF + col],     acc[mt][nt][0]);
            atomicAdd(&C[(row)     * FF + col + 1], acc[mt][nt][1]);
            atomicAdd(&C[(row + 8) * FF + col],     acc[mt][nt][2]);
            atomicAdd(&C[(row + 8) * FF + col + 1], acc[mt][nt][3]);
        }
}

/* ---------------- qprep: grid (32,4), MLP-batched ------------------------- */
__global__ __launch_bounds__(256) void qprep_kernel(const int* __restrict__ ci) {
    int b = blockIdx.x, seg = blockIdx.y, t = threadIdx.x;
    float pos = (float)ci[b];
    const float* qb = g_q + b * HH * DD;
    float4* qf4 = (float4*)(g_qf + b * HH * DD);

    int fid = seg * 256 + t;
    int kd = fid >> 6, mt = (fid >> 5) & 1, cc = (fid >> 3) & 3, gg = fid & 7;
    int r0 = mt * 16 + gg, r1 = r0 + 8;
    int d0 = 8 * kd + cc, d1 = d0 + 4;

    float a00 = qb[r0 * DD + d0];
    float a01 = qb[r1 * DD + d0];
    float o00 = qb[r0 * DD + (d0 ^ 64)];
    float o01 = qb[r1 * DD + (d0 ^ 64)];
    float a10 = qb[r0 * DD + d1];
    float a11 = qb[r1 * DD + d1];
    float o10 = qb[r0 * DD + (d1 ^ 64)];
    float o11 = qb[r1 * DD + (d1 ^ 64)];
    float f0 = g_freq[d0 & 63], f1 = g_freq[d1 & 63];

    float s0, c0, s1, c1;
    sincosf(pos * f0, &s0, &c0);
    sincosf(pos * f1, &s1, &c1);

    float sgn0 = (d0 < 64) ? -1.f : 1.f;
    float sgn1 = (d1 < 64) ? -1.f : 1.f;
    float4 hi;
    hi.x = tff((a00 * c0 + sgn0 * o00 * s0) * SCALE);
    hi.y = tff((a01 * c0 + sgn0 * o01 * s0) * SCALE);
    hi.z = tff((a10 * c1 + sgn1 * o10 * s1) * SCALE);
    hi.w = tff((a11 * c1 + sgn1 * o11 * s1) * SCALE);
    int sfid = kd * 64 + mt * 32 + cc * 8 + ((gg + 2 * cc) & 7);
    qf4[sfid] = hi;

    if (seg == 0 && t < 128) {
        float a = g_k[b * DD + t];
        float o = g_k[b * DD + (t ^ 64)];
        float si, co;
        sincosf(pos * g_freq[t & 63], &si, &co);
        g_kr[b * DD + t] = (t < 64) ? (a * co - o * si) : (a * co + o * si);
    }
}

/* ---------------- flash-decode attention v9: WIN=32, 3 CTAs/SM ------------
 * smem floats: qf 4096 | psh 32x36 | ppack 1024 | kbuf 128x40 | vbuf 128x36
 *            = 16,000 floats = 64,000 B -> 3 CTAs/SM (24 warps).
 * QK: warp w -> h-tile (w>>2), l-octet (w&3). PV: warp w -> d [16w,16w+16). */
__global__ __launch_bounds__(256, 3) void attn_kernel(
        const float* __restrict__ Kc, const float* __restrict__ Vc,
        const int* __restrict__ ci) {
    extern __shared__ float sm[];
    float4* qfh4 = (float4*)sm;                 /* 1024 float4 */
    float*  psh  = sm + 4096;                   /* 1152 */
    float*  ppkf = sm + 5248;                   /* 1024 */
    float4* ppk4 = (float4*)ppkf;
    float*  kbuf = sm + 6272;                   /* 5120 */
    float*  vbuf = sm + 11392;                  /* 4608 */

    int b = blockIdx.x, sp = blockIdx.y;
    int idx = ci[b];
    int c0  = sp * CH;
    if (c0 > idx) return;

    int t = threadIdx.x, w = t >> 5, lane = t & 31;
    int g = lane >> 2, c = lane & 3;
    int mt = w >> 2, wl = w & 3;

    const float* Kb = Kc + (size_t)b * DD * LL;
    const float* Vb = Vc + (size_t)b * DD * LL;

    auto fillK = [&](int wi) {
        uint32_t dst = s2u(kbuf);
        const float* src = Kb + c0 + wi * WIN;
#pragma unroll
        for (int p = 0; p < 4; p++) {
            int i = t + p * 256; int d = i >> 3, u = i & 7;
            cpa16(dst + (uint32_t)(d * LDW + 4 * u) * 4, src + (size_t)d * LL + 4 * u);
        }
        cpcommit();
    };
    auto fillV = [&](int wi) {
        uint32_t dst = s2u(vbuf);
        const float* src = Vb + c0 + wi * WIN;
#pragma unroll
        for (int p = 0; p < 4; p++) {
            int i = t + p * 256; int d = i >> 3, u = i & 7;
            cpa16(dst + (uint32_t)(d * LDV + 4 * u) * 4, src + (size_t)d * LL + 4 * u);
        }
        cpcommit();
    };

    /* Q fragments (group 0), K0 (group 1), V0 (group 2) */
    {
        uint32_t dst = s2u(qfh4);
        const float* src = g_qf + b * HH * DD;
#pragma unroll
        for (int p = 0; p < 4; p++) {
            int i = t + p * 256;
            cpa16(dst + (uint32_t)i * 16, src + i * 4);
        }
        cpcommit();
    }
    fillK(0);
    fillV(0);

    int swz = c * 8 + ((g + 2 * c) & 7);

    float m_r[4] = {-1e30f, -1e30f, -1e30f, -1e30f};
    float s_r[4] = {0.f, 0.f, 0.f, 0.f};
    float acco[2][2][4];
#pragma unroll
    for (int m2 = 0; m2 < 2; m2++)
#pragma unroll
        for (int nt = 0; nt < 2; nt++)
#pragma unroll
            for (int r = 0; r < 4; r++) acco[m2][nt][r] = 0.f;

    for (int wi = 0; wi < 8; wi++) {
        int l0w = c0 + wi * WIN;
        int hot = (idx >= l0w) && (idx < l0w + WIN);
        int li = idx - l0w;

        cpwait1();              /* K_wi ready (V_wi may be pending) */
        __syncthreads();
        if (hot) {
            if (t < 128) kbuf[t * LDW + li] += g_kr[b * DD + t];
            __syncthreads();
        }

        /* ---- QK: 1 m16n8 tile per warp ---- */
        float accq[4] = {0.f, 0.f, 0.f, 0.f};
#pragma unroll
        for (int kd = 0; kd < 16; kd++) {
            float4 ah = qfh4[kd * 64 + mt * 32 + swz];
            float b0 = kbuf[(kd * 8 + c)     * LDW + wl * 8 + g];
            float b1 = kbuf[(kd * 8 + c + 4) * LDW + wl * 8 + g];
            uint32_t bb[2] = {f2tf(b0), f2tf(b1)};
            mma8(accq, (const uint32_t*)&ah, bb);
        }
        {
            int r0 = mt * 16 + g, cb = wl * 8 + 2 * c;
            psh[r0 * LDP + cb]           = accq[0];
            psh[r0 * LDP + cb + 1]       = accq[1];
            psh[(r0 + 8) * LDP + cb]     = accq[2];
            psh[(r0 + 8) * LDP + cb + 1] = accq[3];
        }
        __syncthreads();        /* logits visible; kbuf free */
        if (wi < 7) fillK(wi + 1);

        /* ---- online softmax: warp w owns heads 4w..4w+3; lane -> l=lane -- */
#pragma unroll
        for (int hj = 0; hj < 4; hj++) {
            int h = 4 * w + hj;
            float f = psh[h * LDP + lane];
            if (l0w + WIN - 1 > idx && l0w + lane > idx) f = -1e30f;
            float tm = f;
            tm = fmaxf(tm, __shfl_xor_sync(0xffffffffu, tm, 16));
            tm = fmaxf(tm, __shfl_xor_sync(0xffffffffu, tm, 8));
            tm = fmaxf(tm, __shfl_xor_sync(0xffffffffu, tm, 4));
            tm = fmaxf(tm, __shfl_xor_sync(0xffffffffu, tm, 2));
            tm = fmaxf(tm, __shfl_xor_sync(0xffffffffu, tm, 1));
            float mn = fmaxf(m_r[hj], tm);
            float co = __expf(m_r[hj] - mn);
            float p0 = __expf(f - mn);
            float ls = p0;
            ls += __shfl_xor_sync(0xffffffffu, ls, 16);
            ls += __shfl_xor_sync(0xffffffffu, ls, 8);
            ls += __shfl_xor_sync(0xffffffffu, ls, 4);
            ls += __shfl_xor_sync(0xffffffffu, ls, 2);
            ls += __shfl_xor_sync(0xffffffffu, ls, 1);
            s_r[hj] = s_r[hj] * co + ls;
            m_r[hj] = mn;

            /* fragment-packed prob store (1 per lane) */
            int half = h >> 4, mt2 = (h >> 3) & 1, gp = h & 7;
            int kl = lane >> 3, cpos = lane & 7;
            int hi4 = cpos >> 2, cp = cpos & 3, sk = kl >> 1;
            int rowbase = (kl * 64 + half * 32 + ((gp + kl) & 7) * 4) * 4
                          + mt2 + 2 * hi4;
            ppkf[rowbase + ((cp + sk) & 3) * 4] = tff(p0);
            if (lane == 0) psh[h * LDP + 32] = co;
        }

        if (wi == 7) cpwait0(); else cpwait1();   /* V_wi ready */
        __syncthreads();
        if (hot) {
            if (t < 128) vbuf[t * LDV + li] += g_v[b * DD + t];
            __syncthreads();
        }

        /* rescale PV accumulators */
        {
            float s0 = psh[(g)      * LDP + 32];
            float s1 = psh[(g + 8)  * LDP + 32];
            float s2 = psh[(g + 16) * LDP + 32];
            float s3 = psh[(g + 24) * LDP + 32];
#pragma unroll
            for (int nt = 0; nt < 2; nt++) {
                acco[0][nt][0] *= s0; acco[0][nt][1] *= s0;
                acco[0][nt][2] *= s1; acco[0][nt][3] *= s1;
                acco[1][nt][0] *= s2; acco[1][nt][1] *= s2;
                acco[1][nt][2] *= s3; acco[1][nt][3] *= s3;
            }
        }

        /* ---- PV: single-term tf32 V, 4 k-steps ---- */
#pragma unroll
        for (int kl = 0; kl < 4; kl++) {
            int pidx = kl * 64 + ((g + kl) & 7) * 4 + ((c + (kl >> 1)) & 3);
            float4 ap0f = ppk4[pidx];
            float4 ap1f = ppk4[pidx + 32];
#pragma unroll
            for (int nt = 0; nt < 2; nt++) {
                int d = w * 16 + nt * 8 + g;
                float v0 = vbuf[d * LDV + kl * 8 + c];
                float v1 = vbuf[d * LDV + kl * 8 + c + 4];
                uint32_t bh[2] = {f2tf(v0), f2tf(v1)};
                mma8(acco[0][nt], (const uint32_t*)&ap0f, bh);
                mma8(acco[1][nt], (const uint32_t*)&ap1f, bh);
            }
        }
        __syncthreads();        /* vbuf + psh + ppack free */
        if (wi < 7) fillV(wi + 1);
    }

    /* write partials */
    int pb = (b * NSPLIT + sp) * HH;
    if (lane == 0) {
#pragma unroll
        for (int hj = 0; hj < 4; hj++) {
            g_pm[pb + 4 * w + hj]   = m_r[hj];
            g_psum[pb + 4 * w + hj] = s_r[hj];
        }
    }
#pragma unroll
    for (int m2 = 0; m2 < 2; m2++)
#pragma unroll
        for (int nt = 0; nt < 2; nt++) {
            int h0 = m2 * 16 + g;
            int dd = w * 16 + nt * 8 + 2 * c;
            g_po[(size_t)(pb + h0) * DD + dd]         = acco[m2][nt][0];
            g_po[(size_t)(pb + h0) * DD + dd + 1]     = acco[m2][nt][1];
            g_po[(size_t)(pb + h0 + 8) * DD + dd]     = acco[m2][nt][2];
            g_po[(size_t)(pb + h0 + 8) * DD + dd + 1] = acco[m2][nt][3];
        }
}

/* ---------------- combine (also zeroes `out`) ----------------------------- */
__global__ void combine_kernel(const int* __restrict__ ci, float* __restrict__ out) {
    int bh = blockIdx.x;
    int b = bh >> 5, h = bh & 31;
    int d = threadIdx.x;
    out[bh * 128 + d] = 0.f;
    int nv = (ci[b] >> 8) + 1;
    float m = -1e30f;
    for (int s = 0; s < nv; s++)
        m = fmaxf(m, g_pm[(b * NSPLIT + s) * HH + h]);
    float S = 0.f, acc = 0.f;
    for (int s = 0; s < nv; s++) {
        int ib = (b * NSPLIT + s) * HH + h;
        float w = __expf(g_pm[ib] - m);
        S   += w * g_psum[ib];
        acc += w * g_po[(size_t)ib * DD + d];
    }
    g_attn[(b * HH + h) * DD + d] = acc / S;
}

/* ---------------- launch ------------------------------------------------- */
extern "C" void kernel_launch(void* const* d_in, const int* in_sizes, int n_in,
                              void* d_out, int out_size) {
    const float* x  = (const float*)d_in[0];
    const float* Kc = (const float*)d_in[1];
    const float* Vc = (const float*)d_in[2];
    const float* Wq = (const float*)d_in[3];
    const float* Wk = (const float*)d_in[4];
    const float* Wv = (const float*)d_in[5];
    const float* Wo = (const float*)d_in[6];
    const int*   ci = (const int*)d_in[7];
    float* out = (float*)d_out;

    float *qp, *ap;
    cudaGetSymbolAddress((void**)&qp, g_q);
    cudaGetSymbolAddress((void**)&ap, g_attn);

    cudaFuncSetAttribute(qkvproj_kernel,
                         cudaFuncAttributeMaxDynamicSharedMemorySize, 101376);
    cudaFuncSetAttribute(ogemm_kernel,
                         cudaFuncAttributeMaxDynamicSharedMemorySize, 101376);
    cudaFuncSetAttribute(attn_kernel,
                         cudaFuncAttributeMaxDynamicSharedMemorySize, 64000);

    qkvproj_kernel<<<320, 256, 101376>>>(x, Wq, Wk, Wv, qp);
    qprep_kernel<<<dim3(32, 4), 256>>>(ci);
    attn_kernel<<<dim3(32, NSPLIT), 256, 64000>>>(Kc, Vc, ci);
    combine_kernel<<<1024, 128>>>(ci, out);
    ogemm_kernel<<<dim3(16, 17), 256, 101376>>>(ap, Wo, out);
}